// round 9
// baseline (speedup 1.0000x reference)
#include <cuda_runtime.h>
#include <cuda_bf16.h>

#define WARPS_PER_BLOCK 8
#define NT 32
#define MC 4
#define NITER_MAX 64
#define LOG2E 1.4426950408889634f

union f2u { float2 f; unsigned long long u; };

static __device__ __forceinline__ float2 fma2(float2 a, float2 b, float2 c) {
    f2u A, Bv, C, D; A.f = a; Bv.f = b; C.f = c;
    asm("fma.rn.f32x2 %0, %1, %2, %3;" : "=l"(D.u) : "l"(A.u), "l"(Bv.u), "l"(C.u));
    return D.f;
}
static __device__ __forceinline__ float2 mul2(float2 a, float2 b) {
    f2u A, Bv, D; A.f = a; Bv.f = b;
    asm("mul.rn.f32x2 %0, %1, %2;" : "=l"(D.u) : "l"(A.u), "l"(Bv.u));
    return D.f;
}
static __device__ __forceinline__ float2 add2(float2 a, float2 b) {
    f2u A, Bv, D; A.f = a; Bv.f = b;
    asm("add.rn.f32x2 %0, %1, %2;" : "=l"(D.u) : "l"(A.u), "l"(Bv.u));
    return D.f;
}
static __device__ __forceinline__ float rcp_fast(float x) {
    float r; asm("rcp.approx.f32 %0, %1;" : "=f"(r) : "f"(x)); return r;
}

// One warp per batch element. Lane i owns row i of HH as 16 float2 regs and
// the state Gn = -G*log2e as 2 float2. Packed fma.rn.f32x2 on the heavy FMA
// blocks; max-free softmax; exp2(Gn) hoisted so MUFU overlaps.
// __launch_bounds__(256,4) caps regs at 64 -> 32 warps/SM.
__global__ void __launch_bounds__(WARPS_PER_BLOCK * 32, 4)
cmdnet_kernel(const float* __restrict__ yt,
              const float* __restrict__ Ht,
              const float* __restrict__ sigmat0,
              const float* __restrict__ m_c,
              const float* __restrict__ alpha,
              const float* __restrict__ taui,
              const float* __restrict__ delta,
              float* __restrict__ out,
              int B, int NR, int NITER)
{
    __shared__ __align__(16) float4 s_lasc[NITER_MAX];  // la_j * scale_it * log2e
    __shared__ __align__(16) float4 s_p1[NITER_MAX];    // {-sc, -sc, -ta, d*log2e}
    __shared__ float s_la[MC];                           // log(alpha_j)
    __shared__ float s_tauN, s_tauNl2;                   // |taui[N]|, |taui[N]|*log2e
    __shared__ __align__(16) float s_stage[WARPS_PER_BLOCK][2][NT];
    __shared__ __align__(16) float s_xt[2][WARPS_PER_BLOCK][NT];

    const int tid   = threadIdx.x;
    const int wslot = tid >> 5;
    const int lane  = tid & 31;

    if (tid < NITER) {
        float ta = fabsf(taui[tid]);
        float scale_raw = (tid == 0) ? 1.0f : ta;     // first_iter softmax scale = 1
        float sc = scale_raw * LOG2E;
        float4 l;
        l.x = logf(alpha[0]) * sc;
        l.y = logf(alpha[1]) * sc;
        l.z = logf(alpha[2]) * sc;
        l.w = logf(alpha[3]) * sc;
        s_lasc[tid] = l;
        float4 p;
        p.x = -scale_raw;
        p.y = -scale_raw;
        p.z = -ta;
        p.w = delta[tid] * LOG2E;
        s_p1[tid] = p;
    }
    if (tid < MC) s_la[tid] = logf(alpha[tid]);
    if (tid == 0) {
        float tn = fabsf(taui[NITER]);
        s_tauN   = tn;
        s_tauNl2 = tn * LOG2E;
    }
    __syncthreads();

    const int b = blockIdx.x * WARPS_PER_BLOCK + wslot;
    if (b >= B) return;

    const float* Hb = Ht + (size_t)b * NR * NT;
    const float* yb = yt + (size_t)b * NR;

    // ---------------- Phase 1: HH row (per lane, packed f32x2) + yH ----------
    // 2-row stage groups: tiny live set so the 64-reg cap holds without
    // spilling the phase-2 hot loop.
    float2 hh2[NT / 2];
    #pragma unroll
    for (int k = 0; k < NT / 2; k++) hh2[k] = make_float2(0.0f, 0.0f);
    float yH = 0.0f;

    for (int r0 = 0; r0 < NR; r0 += 2) {
        float h0 = Hb[(r0 + 0) * NT + lane];             // coalesced 128B/row
        float h1 = Hb[(r0 + 1) * NT + lane];
        s_stage[wslot][0][lane] = h0;
        s_stage[wslot][1][lane] = h1;
        yH = fmaf(yb[r0 + 0], h0, yH);                   // broadcast LDG
        yH = fmaf(yb[r0 + 1], h1, yH);
        __syncwarp();
        const float2 h20 = make_float2(h0, h0);
        const float2 h21 = make_float2(h1, h1);
        #pragma unroll
        for (int kk = 0; kk < 8; kk++) {
            float4 v0 = *reinterpret_cast<const float4*>(&s_stage[wslot][0][4 * kk]);
            float4 v1 = *reinterpret_cast<const float4*>(&s_stage[wslot][1][4 * kk]);
            hh2[2 * kk + 0] = fma2(h20, make_float2(v0.x, v0.y), hh2[2 * kk + 0]);
            hh2[2 * kk + 1] = fma2(h20, make_float2(v0.z, v0.w), hh2[2 * kk + 1]);
            hh2[2 * kk + 0] = fma2(h21, make_float2(v1.x, v1.y), hh2[2 * kk + 0]);
            hh2[2 * kk + 1] = fma2(h21, make_float2(v1.z, v1.w), hh2[2 * kk + 1]);
        }
        __syncwarp();
    }

    // ---------------- Phase 2: 64 iterations ----------------
    float2 m2[2];
    m2[0] = make_float2(m_c[0], m_c[1]);
    m2[1] = make_float2(m_c[2], m_c[3]);

    float2 Gn2[2] = {make_float2(0.f, 0.f), make_float2(0.f, 0.f)}; // -G*log2e
    float sig2;
    { float s = sigmat0[b]; sig2 = s * s; }
    const float2 sig2_2  = make_float2(sig2, sig2);
    const float2 nsig2_2 = make_float2(-sig2, -sig2);

    float e0, e1, e2, e3;
    float inv = 0.0f, xt = 0.0f;

    #pragma unroll 2
    for (int it = 0; it < NITER; it++) {
        const float4 lasc = s_lasc[it];
        const float4 p    = s_p1[it];     // {-sc, -sc, -ta, d*log2e}
        const float2 sc2  = make_float2(p.x, p.y);
        const int buf = it & 1;

        // barrier term first: depends only on loop-carried Gn -> MUFU overlaps
        const float2 eg0 = make_float2(exp2f(Gn2[0].x), exp2f(Gn2[0].y)); // exp(-G)
        const float2 eg1 = make_float2(exp2f(Gn2[1].x), exp2f(Gn2[1].y));
        float2 t0 = fma2(nsig2_2, eg0, sig2_2);  // sig2*(1-exp(-G))
        float2 t1 = fma2(nsig2_2, eg1, sig2_2);

        // z (log2 domain) = lasc - Gn*scale; max-free softmax
        float2 z0 = fma2(sc2, Gn2[0], make_float2(lasc.x, lasc.y));
        float2 z1 = fma2(sc2, Gn2[1], make_float2(lasc.z, lasc.w));
        e0 = exp2f(z0.x); e1 = exp2f(z0.y);
        e2 = exp2f(z1.x); e3 = exp2f(z1.y);
        float sum = (e0 + e1) + (e2 + e3);
        inv = rcp_fast(sum);

        // soft symbol: xt = (sum_j e_j m_j) * inv
        float em = e0 * m2[0].x;
        em = fmaf(e1, m2[0].y, em);
        em = fmaf(e2, m2[1].x, em);
        em = fmaf(e3, m2[1].y, em);
        xt = em * inv;

        // broadcast xt across the warp (double-buffered), packed xHH dot (4 accs)
        s_xt[buf][wslot][lane] = xt;
        __syncwarp();
        float2 a0 = make_float2(0.f, 0.f), a1 = make_float2(0.f, 0.f);
        float2 a2 = make_float2(0.f, 0.f), a3 = make_float2(0.f, 0.f);
        #pragma unroll
        for (int kk = 0; kk < 4; kk++) {
            float4 v0 = *reinterpret_cast<const float4*>(&s_xt[buf][wslot][8 * kk]);
            float4 v1 = *reinterpret_cast<const float4*>(&s_xt[buf][wslot][8 * kk + 4]);
            a0 = fma2(make_float2(v0.x, v0.y), hh2[4 * kk + 0], a0);
            a1 = fma2(make_float2(v0.z, v0.w), hh2[4 * kk + 1], a1);
            a2 = fma2(make_float2(v1.x, v1.y), hh2[4 * kk + 2], a2);
            a3 = fma2(make_float2(v1.z, v1.w), hh2[4 * kk + 3], a3);
        }
        float2 as = add2(add2(a0, a1), add2(a2, a3));
        float acc = as.x + as.y;

        // grad_L_j = t_j + ci * e_j*(m_j - xt),  ci = ta*(xHH-yH)*inv
        const float c  = (yH - acc) * p.z;       // = ta*(acc - yH)
        const float ci = c * inv;
        const float2 ci2  = make_float2(ci, ci);
        const float2 dl2  = make_float2(p.w, p.w);
        const float2 nxt2 = make_float2(-xt, -xt);
        float2 d0 = add2(m2[0], nxt2);           // m - xt
        float2 d1 = add2(m2[1], nxt2);
        float2 w0 = mul2(make_float2(e0, e1), d0);
        float2 w1 = mul2(make_float2(e2, e3), d1);
        float2 g0 = fma2(ci2, w0, t0);
        float2 g1 = fma2(ci2, w1, t1);
        Gn2[0] = fma2(dl2, g0, Gn2[0]);          // Gn += d*log2e*gl
        Gn2[1] = fma2(dl2, g1, Gn2[1]);
    }

    // ---------------- Final layer: max-free softmax + soft symbol ------------
    float f[MC];
    {
        const float tl2 = s_tauNl2, tn = s_tauN;
        const float2 ntn2 = make_float2(-tn, -tn);
        float2 z0 = fma2(ntn2, Gn2[0], make_float2(s_la[0] * tl2, s_la[1] * tl2));
        float2 z1 = fma2(ntn2, Gn2[1], make_float2(s_la[2] * tl2, s_la[3] * tl2));
        e0 = exp2f(z0.x); e1 = exp2f(z0.y);
        e2 = exp2f(z1.x); e3 = exp2f(z1.y);
        float sum = (e0 + e1) + (e2 + e3);
        float iv = __fdividef(1.0f, sum);
        f[0] = e0 * iv; f[1] = e1 * iv; f[2] = e2 * iv; f[3] = e3 * iv;
        float em = f[0] * m2[0].x;
        em = fmaf(f[1], m2[0].y, em);
        em = fmaf(f[2], m2[1].x, em);
        em = fmaf(f[3], m2[1].y, em);
        xt = em;
    }

    // ---------------- Write out: ft [B,NT,MC] then xt [B,NT] ----------------
    const size_t base = (size_t)b * NT + lane;
    float4 o;
    o.x = f[0]; o.y = f[1]; o.z = f[2]; o.w = f[3];
    *reinterpret_cast<float4*>(&out[base * MC]) = o;     // coalesced 16B stores
    out[(size_t)B * NT * MC + base] = xt;
}

extern "C" void kernel_launch(void* const* d_in, const int* in_sizes, int n_in,
                              void* d_out, int out_size)
{
    const float* yt     = (const float*)d_in[0];
    const float* Ht     = (const float*)d_in[1];
    const float* sig    = (const float*)d_in[2];
    const float* m      = (const float*)d_in[3];
    const float* alpha  = (const float*)d_in[4];
    const float* taui   = (const float*)d_in[5];
    const float* delta  = (const float*)d_in[6];

    const int B     = in_sizes[2];
    const int NR    = in_sizes[0] / B;
    const int NITER = in_sizes[6];

    const int blocks = (B + WARPS_PER_BLOCK - 1) / WARPS_PER_BLOCK;
    cmdnet_kernel<<<blocks, WARPS_PER_BLOCK * 32>>>(
        yt, Ht, sig, m, alpha, taui, delta, (float*)d_out, B, NR, NITER);
}

// round 10
// speedup vs baseline: 1.0372x; 1.0372x over previous
#include <cuda_runtime.h>
#include <cuda_bf16.h>

#define WARPS_PER_BLOCK 8
#define NT 32
#define MC 4
#define NITER_MAX 64
#define LOG2E 1.4426950408889634f

union f2u { float2 f; unsigned long long u; };

static __device__ __forceinline__ float2 fma2(float2 a, float2 b, float2 c) {
    f2u A, Bv, C, D; A.f = a; Bv.f = b; C.f = c;
    asm("fma.rn.f32x2 %0, %1, %2, %3;" : "=l"(D.u) : "l"(A.u), "l"(Bv.u), "l"(C.u));
    return D.f;
}
static __device__ __forceinline__ float2 mul2(float2 a, float2 b) {
    f2u A, Bv, D; A.f = a; Bv.f = b;
    asm("mul.rn.f32x2 %0, %1, %2;" : "=l"(D.u) : "l"(A.u), "l"(Bv.u));
    return D.f;
}
static __device__ __forceinline__ float2 add2(float2 a, float2 b) {
    f2u A, Bv, D; A.f = a; Bv.f = b;
    asm("add.rn.f32x2 %0, %1, %2;" : "=l"(D.u) : "l"(A.u), "l"(Bv.u));
    return D.f;
}
static __device__ __forceinline__ float rcp_fast(float x) {
    float r; asm("rcp.approx.f32 %0, %1;" : "=f"(r) : "f"(x)); return r;
}

// One warp per batch element. Quad-split HH ownership: lane (m = lane&7,
// q = lane>>3) holds cols [8q,8q+8) of rows {m,m+8,m+16,m+24} as 16 float2.
// Per-lane softmax state is for row = lane. The xHH dot needs only 2 broadcast
// LDS.128 per iter + a 2-stage reduce-scatter butterfly (3 SHFL).
__global__ void __launch_bounds__(WARPS_PER_BLOCK * 32, 4)
cmdnet_kernel(const float* __restrict__ yt,
              const float* __restrict__ Ht,
              const float* __restrict__ sigmat0,
              const float* __restrict__ m_c,
              const float* __restrict__ alpha,
              const float* __restrict__ taui,
              const float* __restrict__ delta,
              float* __restrict__ out,
              int B, int NR, int NITER)
{
    __shared__ __align__(16) float4 s_lasc[NITER_MAX];  // la_j * scale_it * log2e
    __shared__ __align__(16) float4 s_p1[NITER_MAX];    // {-sc, -sc, -ta, d*log2e}
    __shared__ float s_la[MC];
    __shared__ float s_tauN, s_tauNl2;
    __shared__ __align__(16) float s_stage[WARPS_PER_BLOCK][2][NT];
    __shared__ __align__(16) float s_xt[2][WARPS_PER_BLOCK][NT];

    const int tid   = threadIdx.x;
    const int wslot = tid >> 5;
    const int lane  = tid & 31;
    const int m     = lane & 7;         // row-group member
    const int q     = lane >> 3;        // column-quad

    if (tid < NITER) {
        float ta = fabsf(taui[tid]);
        float scale_raw = (tid == 0) ? 1.0f : ta;     // first_iter softmax scale = 1
        float sc = scale_raw * LOG2E;
        float4 l;
        l.x = logf(alpha[0]) * sc;
        l.y = logf(alpha[1]) * sc;
        l.z = logf(alpha[2]) * sc;
        l.w = logf(alpha[3]) * sc;
        s_lasc[tid] = l;
        s_p1[tid] = make_float4(-scale_raw, -scale_raw, -ta, delta[tid] * LOG2E);
    }
    if (tid < MC) s_la[tid] = logf(alpha[tid]);
    if (tid == 0) {
        float tn = fabsf(taui[NITER]);
        s_tauN   = tn;
        s_tauNl2 = tn * LOG2E;
    }
    __syncthreads();

    const int b = blockIdx.x * WARPS_PER_BLOCK + wslot;
    if (b >= B) return;

    const float* Hb = Ht + (size_t)b * NR * NT;
    const float* yb = yt + (size_t)b * NR;

    // ---------------- Phase 1: quad-split HH + per-row yH ----------------
    // hhq[j][c] = HH[m+8j][8q+2c .. 8q+2c+1]
    float2 hhq[4][4];
    #pragma unroll
    for (int j = 0; j < 4; j++)
        #pragma unroll
        for (int c = 0; c < 4; c++) hhq[j][c] = make_float2(0.0f, 0.0f);
    float yH = 0.0f;

    for (int r0 = 0; r0 < NR; r0 += 2) {
        float h0 = Hb[(r0 + 0) * NT + lane];             // own column (coalesced)
        float h1 = Hb[(r0 + 1) * NT + lane];
        s_stage[wslot][0][lane] = h0;
        s_stage[wslot][1][lane] = h1;
        yH = fmaf(yb[r0 + 0], h0, yH);                   // row = lane
        yH = fmaf(yb[r0 + 1], h1, yH);
        __syncwarp();
        #pragma unroll
        for (int rr = 0; rr < 2; rr++) {
            // my 8 columns of this row
            float4 va = *reinterpret_cast<const float4*>(&s_stage[wslot][rr][8 * q]);
            float4 vb = *reinterpret_cast<const float4*>(&s_stage[wslot][rr][8 * q + 4]);
            // my 4 row values of this row
            #pragma unroll
            for (int j = 0; j < 4; j++) {
                float hr = s_stage[wslot][rr][m + 8 * j];
                const float2 h2 = make_float2(hr, hr);
                hhq[j][0] = fma2(h2, make_float2(va.x, va.y), hhq[j][0]);
                hhq[j][1] = fma2(h2, make_float2(va.z, va.w), hhq[j][1]);
                hhq[j][2] = fma2(h2, make_float2(vb.x, vb.y), hhq[j][2]);
                hhq[j][3] = fma2(h2, make_float2(vb.z, vb.w), hhq[j][3]);
            }
        }
        __syncwarp();
    }

    // ---------------- Phase 2: 64 iterations ----------------
    float2 m2[2];
    m2[0] = make_float2(m_c[0], m_c[1]);
    m2[1] = make_float2(m_c[2], m_c[3]);

    float2 Gn2[2] = {make_float2(0.f, 0.f), make_float2(0.f, 0.f)}; // -G*log2e
    float sig2;
    { float s = sigmat0[b]; sig2 = s * s; }
    const float2 sig2_2  = make_float2(sig2, sig2);
    const float2 nsig2_2 = make_float2(-sig2, -sig2);

    const bool qb0 = (q & 1) != 0;      // butterfly selectors (compile to SEL)
    const bool qb1 = (q & 2) != 0;

    float e0, e1, e2, e3;
    float inv = 0.0f, xt = 0.0f;

    #pragma unroll 2
    for (int it = 0; it < NITER; it++) {
        const float4 lasc = s_lasc[it];
        const float4 p    = s_p1[it];     // {-sc, -sc, -ta, d*log2e}
        const float2 sc2  = make_float2(p.x, p.y);
        const int buf = it & 1;

        // barrier term first (depends only on loop-carried Gn)
        const float2 eg0 = make_float2(exp2f(Gn2[0].x), exp2f(Gn2[0].y)); // exp(-G)
        const float2 eg1 = make_float2(exp2f(Gn2[1].x), exp2f(Gn2[1].y));
        float2 t0 = fma2(nsig2_2, eg0, sig2_2);
        float2 t1 = fma2(nsig2_2, eg1, sig2_2);

        // max-free softmax in log2 domain
        float2 z0 = fma2(sc2, Gn2[0], make_float2(lasc.x, lasc.y));
        float2 z1 = fma2(sc2, Gn2[1], make_float2(lasc.z, lasc.w));
        e0 = exp2f(z0.x); e1 = exp2f(z0.y);
        e2 = exp2f(z1.x); e3 = exp2f(z1.y);
        float sum = (e0 + e1) + (e2 + e3);
        inv = rcp_fast(sum);

        float em = e0 * m2[0].x;
        em = fmaf(e1, m2[0].y, em);
        em = fmaf(e2, m2[1].x, em);
        em = fmaf(e3, m2[1].y, em);
        xt = em * inv;                   // soft symbol for row = lane

        // share xt, then quad-split dot: 2 LDS.128 + 16 FFMA2 + butterfly
        s_xt[buf][wslot][lane] = xt;
        __syncwarp();
        float4 v0 = *reinterpret_cast<const float4*>(&s_xt[buf][wslot][8 * q]);
        float4 v1 = *reinterpret_cast<const float4*>(&s_xt[buf][wslot][8 * q + 4]);
        const float2 x0 = make_float2(v0.x, v0.y);
        const float2 x1 = make_float2(v0.z, v0.w);
        const float2 x2 = make_float2(v1.x, v1.y);
        const float2 x3 = make_float2(v1.z, v1.w);
        float P[4];
        #pragma unroll
        for (int j = 0; j < 4; j++) {
            float2 a = mul2(x0, hhq[j][0]);
            a = fma2(x1, hhq[j][1], a);
            a = fma2(x2, hhq[j][2], a);
            a = fma2(x3, hhq[j][3], a);
            P[j] = a.x + a.y;            // partial dot of row m+8j over my 8 cols
        }
        // reduce-scatter: stage 1 (xor 8) over q-bit0, stage 2 (xor 16) over q-bit1
        float give0 = qb0 ? P[0] : P[1];
        float give1 = qb0 ? P[2] : P[3];
        float keep0 = qb0 ? P[1] : P[0];
        float keep1 = qb0 ? P[3] : P[2];
        float S0 = keep0 + __shfl_xor_sync(0xFFFFFFFFu, give0, 8);  // row m+8*(q&1)
        float S1 = keep1 + __shfl_xor_sync(0xFFFFFFFFu, give1, 8);  // row m+16+8*(q&1)
        float give2 = qb1 ? S0 : S1;
        float keep2 = qb1 ? S1 : S0;
        float acc = keep2 + __shfl_xor_sync(0xFFFFFFFFu, give2, 16); // row = lane

        // grad_L_j = t_j + ci * e_j*(m_j - xt),  ci = ta*(xHH-yH)*inv
        const float c  = (yH - acc) * p.z;       // = ta*(acc - yH)
        const float ci = c * inv;
        const float2 ci2  = make_float2(ci, ci);
        const float2 dl2  = make_float2(p.w, p.w);
        const float2 nxt2 = make_float2(-xt, -xt);
        float2 d0 = add2(m2[0], nxt2);
        float2 d1 = add2(m2[1], nxt2);
        float2 w0 = mul2(make_float2(e0, e1), d0);
        float2 w1 = mul2(make_float2(e2, e3), d1);
        float2 g0 = fma2(ci2, w0, t0);
        float2 g1 = fma2(ci2, w1, t1);
        Gn2[0] = fma2(dl2, g0, Gn2[0]);
        Gn2[1] = fma2(dl2, g1, Gn2[1]);
    }

    // ---------------- Final layer: max-free softmax + soft symbol ------------
    float f[MC];
    {
        const float tl2 = s_tauNl2, tn = s_tauN;
        const float2 ntn2 = make_float2(-tn, -tn);
        float2 z0 = fma2(ntn2, Gn2[0], make_float2(s_la[0] * tl2, s_la[1] * tl2));
        float2 z1 = fma2(ntn2, Gn2[1], make_float2(s_la[2] * tl2, s_la[3] * tl2));
        e0 = exp2f(z0.x); e1 = exp2f(z0.y);
        e2 = exp2f(z1.x); e3 = exp2f(z1.y);
        float sum = (e0 + e1) + (e2 + e3);
        float iv = __fdividef(1.0f, sum);
        f[0] = e0 * iv; f[1] = e1 * iv; f[2] = e2 * iv; f[3] = e3 * iv;
        float em = f[0] * m2[0].x;
        em = fmaf(f[1], m2[0].y, em);
        em = fmaf(f[2], m2[1].x, em);
        em = fmaf(f[3], m2[1].y, em);
        xt = em;
    }

    // ---------------- Write out: ft [B,NT,MC] then xt [B,NT] ----------------
    const size_t base = (size_t)b * NT + lane;
    float4 o;
    o.x = f[0]; o.y = f[1]; o.z = f[2]; o.w = f[3];
    *reinterpret_cast<float4*>(&out[base * MC]) = o;
    out[(size_t)B * NT * MC + base] = xt;
}

extern "C" void kernel_launch(void* const* d_in, const int* in_sizes, int n_in,
                              void* d_out, int out_size)
{
    const float* yt     = (const float*)d_in[0];
    const float* Ht     = (const float*)d_in[1];
    const float* sig    = (const float*)d_in[2];
    const float* m      = (const float*)d_in[3];
    const float* alpha  = (const float*)d_in[4];
    const float* taui   = (const float*)d_in[5];
    const float* delta  = (const float*)d_in[6];

    const int B     = in_sizes[2];
    const int NR    = in_sizes[0] / B;
    const int NITER = in_sizes[6];

    const int blocks = (B + WARPS_PER_BLOCK - 1) / WARPS_PER_BLOCK;
    cmdnet_kernel<<<blocks, WARPS_PER_BLOCK * 32>>>(
        yt, Ht, sig, m, alpha, taui, delta, (float*)d_out, B, NR, NITER);
}